// round 8
// baseline (speedup 1.0000x reference)
#include <cuda_runtime.h>
#include <cuda_fp16.h>

// ---------------------------------------------------------------------------
// LapImage R6 (re-run; previous attempt hit a broker infra failure):
// bucket scatter with embedded original index -> sample kernels write
// DIRECTLY to the output (scattered). Deletes the unpermute pass, g_inv and
// g_res entirely (~40B/pt stream traffic + one launch).
//
// Record = float4(gx, gy, gz, bitcast(orig_idx)).
// Deterministic: atomic order only picks slots; per-point value identical.
// ---------------------------------------------------------------------------

static constexpr int D0 = 32, H0 = 32,  W0 = 32;
static constexpr int D1 = 32, H1 = 64,  W1 = 64;
static constexpr int D2 = 32, H2 = 128, W2 = 128;
static constexpr int D3 = 32, H3 = 256, W3 = 256;
static constexpr int NV0 = D0 * H0 * W0;
static constexpr int NV1 = D1 * H1 * W1;
static constexpr int NV2 = D2 * H2 * W2;
static constexpr int NV3 = D3 * H3 * W3;
static constexpr int NV_TOTAL = NV0 + NV1 + NV2 + NV3;

static constexpr int BVOL = 96 * 96 * 96;   // 884736
static constexpr int NPTS = 4 * BVOL;       // 3538944 = 13824 * 256

// Spatial bins: long in x. 16 x 256 x 32 = 131072 bins, mean 27 pts/bin.
static constexpr int SBX = 16, SBY = 256, SBZ = 32;
static constexpr int NB  = SBX * SBY * SBZ;    // 131072
static constexpr int CAP = 32;                 // one warp per bucket
static constexpr int NSLOTS = NB * CAP;        // 4194304

// ---- volume storage (fp16 half4 voxels, E/O x-pair duplicates) ----
__device__ __align__(16) uint2 g_e0[NV0];  __device__ __align__(16) uint2 g_o0[NV0];
__device__ __align__(16) uint2 g_e1[NV1];  __device__ __align__(16) uint2 g_o1[NV1];
__device__ __align__(16) uint2 g_e2[NV2];  __device__ __align__(16) uint2 g_o2[NV2];
__device__ __align__(16) uint2 g_e3[NV3];  __device__ __align__(16) uint2 g_o3[NV3];

// ---- bucket scratch ----
__device__ int    g_cnt[NB];
__device__ int    g_novf;
__device__ float4 g_sorted[NSLOTS];            // (gx,gy,gz, bitcast idx)
__device__ float4 g_ovf[NPTS];                 // overflow records

// ---------------------------------------------------------------------------
// Pack: [3,D,H,W] fp32 -> half4 voxels in E[i] and O[i-1]; zeros counters.
// ---------------------------------------------------------------------------
__device__ __forceinline__ void pack_one(const float* __restrict__ s, int i, int nv,
                                         uint2* __restrict__ E, uint2* __restrict__ O)
{
    __half h0 = __float2half_rn(s[i]);
    __half h1 = __float2half_rn(s[i + nv]);
    __half h2 = __float2half_rn(s[i + 2 * nv]);
    __half2 lo = __halves2half2(h0, h1);
    __half2 hi = __halves2half2(h2, __ushort_as_half((unsigned short)0));
    uint2 u;
    u.x = *reinterpret_cast<unsigned int*>(&lo);
    u.y = *reinterpret_cast<unsigned int*>(&hi);
    E[i] = u;
    if (i > 0) O[i - 1] = u;
}

__global__ void __launch_bounds__(256) pack_kernel(
    const float* __restrict__ s0, const float* __restrict__ s1,
    const float* __restrict__ s2, const float* __restrict__ s3)
{
    int i = blockIdx.x * 256 + threadIdx.x;
    if (i < NB) g_cnt[i] = 0;
    if (i == 0) g_novf = 0;
    if (i < NV0) { pack_one(s0, i, NV0, g_e0, g_o0); return; }
    i -= NV0;
    if (i < NV1) { pack_one(s1, i, NV1, g_e1, g_o1); return; }
    i -= NV1;
    if (i < NV2) { pack_one(s2, i, NV2, g_e2, g_o2); return; }
    i -= NV2;
    if (i < NV3) { pack_one(s3, i, NV3, g_e3, g_o3); }
}

// ---------------------------------------------------------------------------
// Scatter: single pass; record carries the original index in .w.
// ---------------------------------------------------------------------------
__device__ __forceinline__ int coord_key(float gx, float gy, float gz)
{
    int bx = (int)(fminf(fmaxf((gx + 1.0f) * 0.5f, 0.0f), 0.999999f) * (float)SBX);
    int by = (int)(fminf(fmaxf((gy + 1.0f) * 0.5f, 0.0f), 0.999999f) * (float)SBY);
    int bz = (int)(fminf(fmaxf((gz + 1.0f) * 0.5f, 0.0f), 0.999999f) * (float)SBZ);
    bx = min(bx, SBX - 1); by = min(by, SBY - 1); bz = min(bz, SBZ - 1);
    return (bz * SBY + by) * SBX + bx;
}

__global__ void __launch_bounds__(256) scatter_kernel(const float* __restrict__ coords)
{
    __shared__ float sc[768];
    int t = threadIdx.x;
    int base = blockIdx.x * 256;
    const float4* c4 = reinterpret_cast<const float4*>(coords + (size_t)base * 3);
    if (t < 192) {
        float4 v = __ldg(c4 + t);
        sc[4 * t + 0] = v.x; sc[4 * t + 1] = v.y;
        sc[4 * t + 2] = v.z; sc[4 * t + 3] = v.w;
    }
    __syncthreads();

    float gx = sc[3 * t], gy = sc[3 * t + 1], gz = sc[3 * t + 2];
    int n = base + t;
    float4 rec = make_float4(gx, gy, gz, __int_as_float(n));
    int key = coord_key(gx, gy, gz);
    int c = atomicAdd(&g_cnt[key], 1);
    if (c < CAP) {
        g_sorted[key * CAP + c] = rec;
    } else {
        int j = atomicAdd(&g_novf, 1);
        g_ovf[j] = rec;
    }
}

// ---------------------------------------------------------------------------
// Trilinear sample (half2 x-lerp, fp32 accumulate).
// ---------------------------------------------------------------------------
__device__ __forceinline__ void acc_pair(uint4 q, float w, __half2 fx2,
                                         float& ax, float& ay, float& az)
{
    __half2 a01 = *reinterpret_cast<__half2*>(&q.x);
    __half2 a2j = *reinterpret_cast<__half2*>(&q.y);
    __half2 b01 = *reinterpret_cast<__half2*>(&q.z);
    __half2 b2j = *reinterpret_cast<__half2*>(&q.w);
    __half2 t01 = __hfma2(fx2, __hsub2(b01, a01), a01);
    __half2 t2  = __hfma2(fx2, __hsub2(b2j, a2j), a2j);
    float2 t01f = __half22float2(t01);
    float  t2f  = __low2float(t2);
    ax = fmaf(w, t01f.x, ax);
    ay = fmaf(w, t01f.y, ay);
    az = fmaf(w, t2f,    az);
}

template <int D, int H, int W>
__device__ __forceinline__ void sample_vol(
    const uint2* __restrict__ E, const uint2* __restrict__ O,
    float gx, float gy, float gz,
    float& ax, float& ay, float& az)
{
    const float hx = 0.5f * (float)(W - 1);
    const float hy = 0.5f * (float)(H - 1);
    const float hz = 0.5f * (float)(D - 1);
    float ix = fminf(fmaxf(fmaf(gx, hx, hx), 0.0f), (float)(W - 1));
    float iy = fminf(fmaxf(fmaf(gy, hy, hy), 0.0f), (float)(H - 1));
    float iz = fminf(fmaxf(fmaf(gz, hz, hz), 0.0f), (float)(D - 1));

    int x0 = min((int)ix, W - 2);
    int y0 = min((int)iy, H - 2);
    int z0 = min((int)iz, D - 2);
    float fx = ix - (float)x0;
    float fy = iy - (float)y0;
    float fz = iz - (float)z0;
    __half2 fx2 = __float2half2_rn(fx);

    int r00 = (z0 * H + y0) * W;
    int r01 = r00 + W;
    int r10 = r00 + H * W;
    int r11 = r10 + W;

    int odd = x0 & 1;
    const uint2* arr = odd ? O : E;
    int xo = x0 - odd;

    uint4 q00 = __ldg(reinterpret_cast<const uint4*>(arr + (r00 + xo)));
    uint4 q01 = __ldg(reinterpret_cast<const uint4*>(arr + (r01 + xo)));
    uint4 q10 = __ldg(reinterpret_cast<const uint4*>(arr + (r10 + xo)));
    uint4 q11 = __ldg(reinterpret_cast<const uint4*>(arr + (r11 + xo)));

    float ez = 1.0f - fz, ey = 1.0f - fy;
    acc_pair(q00, ez * ey, fx2, ax, ay, az);
    acc_pair(q01, ez * fy, fx2, ax, ay, az);
    acc_pair(q10, fz * ey, fx2, ax, ay, az);
    acc_pair(q11, fz * fy, fx2, ax, ay, az);
}

// Sample all 4 volumes and write directly to the output at original index n.
__device__ __forceinline__ void sample_and_store(float4 rec, float* __restrict__ out)
{
    float ax = 0.0f, ay = 0.0f, az = 0.0f;
    sample_vol<D0, H0, W0>(g_e0, g_o0, rec.x, rec.y, rec.z, ax, ay, az);
    sample_vol<D1, H1, W1>(g_e1, g_o1, rec.x, rec.y, rec.z, ax, ay, az);
    sample_vol<D2, H2, W2>(g_e2, g_o2, rec.x, rec.y, rec.z, ax, ay, az);
    sample_vol<D3, H3, W3>(g_e3, g_o3, rec.x, rec.y, rec.z, ax, ay, az);

    int n = __float_as_int(rec.w);
    int b = n / BVOL;
    int v = n - b * BVOL;
    float* o = out + (size_t)(b * 3) * BVOL + v;
    o[0]        = ax;
    o[BVOL]     = ay;
    o[2 * BVOL] = az;
}

// ---------------------------------------------------------------------------
// Bucket sample: one warp per bucket; writes directly to out.
// ---------------------------------------------------------------------------
__global__ void __launch_bounds__(256) sample_bucket_kernel(float* __restrict__ out)
{
    int warp = blockIdx.x * 8 + (threadIdx.x >> 5);
    int lane = threadIdx.x & 31;
    int cnt = min(g_cnt[warp], CAP);
    if (lane < cnt) {
        float4 rec = g_sorted[warp * CAP + lane];
        sample_and_store(rec, out);
    }
}

// ---------------------------------------------------------------------------
// Overflow sample: grid-stride; writes directly to out.
// ---------------------------------------------------------------------------
__global__ void __launch_bounds__(256) sample_ovf_kernel(float* __restrict__ out)
{
    int total = g_novf;
    for (int j = blockIdx.x * 256 + threadIdx.x; j < total; j += gridDim.x * 256) {
        sample_and_store(g_ovf[j], out);
    }
}

// ---------------------------------------------------------------------------
// Launch
// ---------------------------------------------------------------------------
extern "C" void kernel_launch(void* const* d_in, const int* in_sizes, int n_in,
                              void* d_out, int out_size)
{
    const float* coords = (const float*)d_in[0];
    const float* img0   = (const float*)d_in[1];
    const float* img1   = (const float*)d_in[2];
    const float* img2   = (const float*)d_in[3];
    const float* img3   = (const float*)d_in[4];
    float*       out    = (float*)d_out;

    pack_kernel<<<NV_TOTAL / 256, 256>>>(img0, img1, img2, img3);
    scatter_kernel<<<NPTS / 256, 256>>>(coords);
    sample_bucket_kernel<<<NB / 8, 256>>>(out);    // 1 warp per bucket
    sample_ovf_kernel<<<2048, 256>>>(out);
}

// round 9
// speedup vs baseline: 1.1549x; 1.1549x over previous
#include <cuda_runtime.h>
#include <cuda_fp16.h>

// ---------------------------------------------------------------------------
// LapImage R8: R5 structure (bucket scatter -> coalesced g_res -> unpermute)
// with: overflow fused into the bucket kernel's tail blocks (one launch less,
// tail overlapped), unpermute at 4 pts/thread (gather MLP), fp32 x-lerp
// restored (half2 lerp bought no perf in R5; reclaims rel_err margin).
//
// R6 lesson: scattered scalar stores inside the L1-bound sample kernel cost
// ~96 wf/warp; one 16B random gather + coalesced stores in a separate pass
// is strictly cheaper. Keep that shape.
// ---------------------------------------------------------------------------

static constexpr int D0 = 32, H0 = 32,  W0 = 32;
static constexpr int D1 = 32, H1 = 64,  W1 = 64;
static constexpr int D2 = 32, H2 = 128, W2 = 128;
static constexpr int D3 = 32, H3 = 256, W3 = 256;
static constexpr int NV0 = D0 * H0 * W0;
static constexpr int NV1 = D1 * H1 * W1;
static constexpr int NV2 = D2 * H2 * W2;
static constexpr int NV3 = D3 * H3 * W3;
static constexpr int NV_TOTAL = NV0 + NV1 + NV2 + NV3;

static constexpr int BVOL = 96 * 96 * 96;   // 884736
static constexpr int NPTS = 4 * BVOL;       // 3538944 = 13824 * 256

// Spatial bins: long in x. 16 x 256 x 32 = 131072 bins, mean 27 pts/bin.
static constexpr int SBX = 16, SBY = 256, SBZ = 32;
static constexpr int NB  = SBX * SBY * SBZ;    // 131072
static constexpr int CAP = 32;                 // one warp per bucket
static constexpr int NSLOTS = NB * CAP;        // 4194304

static constexpr int BUCKET_BLOCKS = NB / 8;   // 16384 (8 warps/block)
static constexpr int OVF_BLOCKS    = 1024;     // tail blocks in same grid

// ---- volume storage (fp16 half4 voxels, E/O x-pair duplicates) ----
__device__ __align__(16) uint2 g_e0[NV0];  __device__ __align__(16) uint2 g_o0[NV0];
__device__ __align__(16) uint2 g_e1[NV1];  __device__ __align__(16) uint2 g_o1[NV1];
__device__ __align__(16) uint2 g_e2[NV2];  __device__ __align__(16) uint2 g_o2[NV2];
__device__ __align__(16) uint2 g_e3[NV3];  __device__ __align__(16) uint2 g_o3[NV3];

// ---- bucket scratch ----
__device__ int    g_cnt[NB];
__device__ int    g_novf;
__device__ int    g_inv[NPTS];                 // orig idx -> result position
__device__ float4 g_sorted[NSLOTS];            // bucketed coord records
__device__ float4 g_ovf[NPTS];                 // overflow records
__device__ float4 g_res[NSLOTS + NPTS];        // results: buckets then overflow

// ---------------------------------------------------------------------------
// Pack: [3,D,H,W] fp32 -> half4 voxels in E[i] and O[i-1]; zeros counters.
// ---------------------------------------------------------------------------
__device__ __forceinline__ void pack_one(const float* __restrict__ s, int i, int nv,
                                         uint2* __restrict__ E, uint2* __restrict__ O)
{
    __half h0 = __float2half_rn(s[i]);
    __half h1 = __float2half_rn(s[i + nv]);
    __half h2 = __float2half_rn(s[i + 2 * nv]);
    __half2 lo = __halves2half2(h0, h1);
    __half2 hi = __halves2half2(h2, __ushort_as_half((unsigned short)0));
    uint2 u;
    u.x = *reinterpret_cast<unsigned int*>(&lo);
    u.y = *reinterpret_cast<unsigned int*>(&hi);
    E[i] = u;
    if (i > 0) O[i - 1] = u;
}

__global__ void __launch_bounds__(256) pack_kernel(
    const float* __restrict__ s0, const float* __restrict__ s1,
    const float* __restrict__ s2, const float* __restrict__ s3)
{
    int i = blockIdx.x * 256 + threadIdx.x;
    if (i < NB) g_cnt[i] = 0;
    if (i == 0) g_novf = 0;
    if (i < NV0) { pack_one(s0, i, NV0, g_e0, g_o0); return; }
    i -= NV0;
    if (i < NV1) { pack_one(s1, i, NV1, g_e1, g_o1); return; }
    i -= NV1;
    if (i < NV2) { pack_one(s2, i, NV2, g_e2, g_o2); return; }
    i -= NV2;
    if (i < NV3) { pack_one(s3, i, NV3, g_e3, g_o3); }
}

// ---------------------------------------------------------------------------
// Scatter: single pass; writes record + inverse-permutation entry.
// ---------------------------------------------------------------------------
__device__ __forceinline__ int coord_key(float gx, float gy, float gz)
{
    int bx = (int)(fminf(fmaxf((gx + 1.0f) * 0.5f, 0.0f), 0.999999f) * (float)SBX);
    int by = (int)(fminf(fmaxf((gy + 1.0f) * 0.5f, 0.0f), 0.999999f) * (float)SBY);
    int bz = (int)(fminf(fmaxf((gz + 1.0f) * 0.5f, 0.0f), 0.999999f) * (float)SBZ);
    bx = min(bx, SBX - 1); by = min(by, SBY - 1); bz = min(bz, SBZ - 1);
    return (bz * SBY + by) * SBX + bx;
}

__global__ void __launch_bounds__(256) scatter_kernel(const float* __restrict__ coords)
{
    __shared__ float sc[768];
    int t = threadIdx.x;
    int base = blockIdx.x * 256;
    const float4* c4 = reinterpret_cast<const float4*>(coords + (size_t)base * 3);
    if (t < 192) {
        float4 v = __ldg(c4 + t);
        sc[4 * t + 0] = v.x; sc[4 * t + 1] = v.y;
        sc[4 * t + 2] = v.z; sc[4 * t + 3] = v.w;
    }
    __syncthreads();

    float gx = sc[3 * t], gy = sc[3 * t + 1], gz = sc[3 * t + 2];
    int n = base + t;
    float4 rec = make_float4(gx, gy, gz, 0.0f);
    int key = coord_key(gx, gy, gz);
    int c = atomicAdd(&g_cnt[key], 1);
    int pos;
    if (c < CAP) {
        pos = key * CAP + c;
        g_sorted[pos] = rec;
    } else {
        int j = atomicAdd(&g_novf, 1);
        g_ovf[j] = rec;
        pos = NSLOTS + j;
    }
    g_inv[n] = pos;          // coalesced in n
}

// ---------------------------------------------------------------------------
// Trilinear sample (fp32 x-lerp, fp32 accumulate).
// ---------------------------------------------------------------------------
__device__ __forceinline__ void acc_pair(uint4 q, float w, float fx,
                                         float& ax, float& ay, float& az)
{
    const __half2* h = reinterpret_cast<const __half2*>(&q);
    float2 a01 = __half22float2(h[0]);
    float  a2  = __low2float(h[1]);
    float2 b01 = __half22float2(h[2]);
    float  b2  = __low2float(h[3]);
    float cx = fmaf(fx, b01.x - a01.x, a01.x);
    float cy = fmaf(fx, b01.y - a01.y, a01.y);
    float cz = fmaf(fx, b2    - a2,    a2);
    ax = fmaf(w, cx, ax);
    ay = fmaf(w, cy, ay);
    az = fmaf(w, cz, az);
}

template <int D, int H, int W>
__device__ __forceinline__ void sample_vol(
    const uint2* __restrict__ E, const uint2* __restrict__ O,
    float gx, float gy, float gz,
    float& ax, float& ay, float& az)
{
    const float hx = 0.5f * (float)(W - 1);
    const float hy = 0.5f * (float)(H - 1);
    const float hz = 0.5f * (float)(D - 1);
    float ix = fminf(fmaxf(fmaf(gx, hx, hx), 0.0f), (float)(W - 1));
    float iy = fminf(fmaxf(fmaf(gy, hy, hy), 0.0f), (float)(H - 1));
    float iz = fminf(fmaxf(fmaf(gz, hz, hz), 0.0f), (float)(D - 1));

    int x0 = min((int)ix, W - 2);
    int y0 = min((int)iy, H - 2);
    int z0 = min((int)iz, D - 2);
    float fx = ix - (float)x0;
    float fy = iy - (float)y0;
    float fz = iz - (float)z0;

    int r00 = (z0 * H + y0) * W;
    int r01 = r00 + W;
    int r10 = r00 + H * W;
    int r11 = r10 + W;

    int odd = x0 & 1;
    const uint2* arr = odd ? O : E;
    int xo = x0 - odd;

    uint4 q00 = __ldg(reinterpret_cast<const uint4*>(arr + (r00 + xo)));
    uint4 q01 = __ldg(reinterpret_cast<const uint4*>(arr + (r01 + xo)));
    uint4 q10 = __ldg(reinterpret_cast<const uint4*>(arr + (r10 + xo)));
    uint4 q11 = __ldg(reinterpret_cast<const uint4*>(arr + (r11 + xo)));

    float ez = 1.0f - fz, ey = 1.0f - fy;
    acc_pair(q00, ez * ey, fx, ax, ay, az);
    acc_pair(q01, ez * fy, fx, ax, ay, az);
    acc_pair(q10, fz * ey, fx, ax, ay, az);
    acc_pair(q11, fz * fy, fx, ax, ay, az);
}

__device__ __forceinline__ float4 sample_all(float gx, float gy, float gz)
{
    float ax = 0.0f, ay = 0.0f, az = 0.0f;
    sample_vol<D0, H0, W0>(g_e0, g_o0, gx, gy, gz, ax, ay, az);
    sample_vol<D1, H1, W1>(g_e1, g_o1, gx, gy, gz, ax, ay, az);
    sample_vol<D2, H2, W2>(g_e2, g_o2, gx, gy, gz, ax, ay, az);
    sample_vol<D3, H3, W3>(g_e3, g_o3, gx, gy, gz, ax, ay, az);
    return make_float4(ax, ay, az, 0.0f);
}

// ---------------------------------------------------------------------------
// Fused sample: first BUCKET_BLOCKS blocks do one warp per bucket (coalesced
// g_res writes); tail OVF_BLOCKS blocks grid-stride the overflow list.
// ---------------------------------------------------------------------------
__global__ void __launch_bounds__(256) sample_kernel()
{
    if (blockIdx.x < BUCKET_BLOCKS) {
        int warp = blockIdx.x * 8 + (threadIdx.x >> 5);
        int lane = threadIdx.x & 31;
        int cnt = min(g_cnt[warp], CAP);
        if (lane < cnt) {
            int pos = warp * CAP + lane;
            float4 c = g_sorted[pos];
            g_res[pos] = sample_all(c.x, c.y, c.z);
        }
    } else {
        int total = g_novf;
        int tid = (blockIdx.x - BUCKET_BLOCKS) * 256 + threadIdx.x;
        for (int j = tid; j < total; j += OVF_BLOCKS * 256) {
            float4 c = g_ovf[j];
            g_res[NSLOTS + j] = sample_all(c.x, c.y, c.z);
        }
    }
}

// ---------------------------------------------------------------------------
// Unpermute: 4 pts/thread (4 independent 16B gathers in flight), coalesced
// output stores.
// ---------------------------------------------------------------------------
__global__ void __launch_bounds__(256) unpermute_kernel(float* __restrict__ out)
{
    int base = blockIdx.x * 1024 + threadIdx.x;

    int p0 = g_inv[base];
    int p1 = g_inv[base + 256];
    int p2 = g_inv[base + 512];
    int p3 = g_inv[base + 768];

    float4 r0 = __ldg(&g_res[p0]);
    float4 r1 = __ldg(&g_res[p1]);
    float4 r2 = __ldg(&g_res[p2]);
    float4 r3 = __ldg(&g_res[p3]);

    #pragma unroll
    for (int k = 0; k < 4; k++) {
        int m = base + k * 256;
        float4 r = (k == 0) ? r0 : (k == 1) ? r1 : (k == 2) ? r2 : r3;
        int b = m / BVOL;
        int v = m - b * BVOL;
        float* o = out + (size_t)(b * 3) * BVOL + v;
        o[0]        = r.x;
        o[BVOL]     = r.y;
        o[2 * BVOL] = r.z;
    }
}

// ---------------------------------------------------------------------------
// Launch
// ---------------------------------------------------------------------------
extern "C" void kernel_launch(void* const* d_in, const int* in_sizes, int n_in,
                              void* d_out, int out_size)
{
    const float* coords = (const float*)d_in[0];
    const float* img0   = (const float*)d_in[1];
    const float* img1   = (const float*)d_in[2];
    const float* img2   = (const float*)d_in[3];
    const float* img3   = (const float*)d_in[4];
    float*       out    = (float*)d_out;

    pack_kernel<<<NV_TOTAL / 256, 256>>>(img0, img1, img2, img3);
    scatter_kernel<<<NPTS / 256, 256>>>(coords);
    sample_kernel<<<BUCKET_BLOCKS + OVF_BLOCKS, 256>>>();
    unpermute_kernel<<<NPTS / 1024, 256>>>(out);
}

// round 10
// speedup vs baseline: 1.1906x; 1.0309x over previous
#include <cuda_runtime.h>
#include <cuda_fp16.h>

// ---------------------------------------------------------------------------
// LapImage R9: VOXEL-ALIGNED spatial bins.
//
// R5-R8 analysis: sample kernel ran ~166 wf/warp because bin edges (power-of-
// two lattices /256, /32) don't align with the align_corners sample lattice
// (scales H-1=255, D-1=31). Within one bin y0 and z0 each straddled 2 values,
// multiplying distinct-lines-per-gather by 4.
//
// Fix: bins ARE the sample lattice: bx=floor(u*16), by=floor(v*255) (== img3
// y0), bz=floor(w*31) (== z0 for ALL volumes since D=32 everywhere).
// NB = 16*255*31 = 126480, mean 28 pts/bin, CAP=32, overflow ~1-2%.
// Within a bucket: one z0, one img3-y0 -> gathers touch ~2 lines, not 8.
// Binning cannot affect values (both paths compute identically).
// ---------------------------------------------------------------------------

static constexpr int D0 = 32, H0 = 32,  W0 = 32;
static constexpr int D1 = 32, H1 = 64,  W1 = 64;
static constexpr int D2 = 32, H2 = 128, W2 = 128;
static constexpr int D3 = 32, H3 = 256, W3 = 256;
static constexpr int NV0 = D0 * H0 * W0;
static constexpr int NV1 = D1 * H1 * W1;
static constexpr int NV2 = D2 * H2 * W2;
static constexpr int NV3 = D3 * H3 * W3;
static constexpr int NV_TOTAL = NV0 + NV1 + NV2 + NV3;

static constexpr int BVOL = 96 * 96 * 96;   // 884736
static constexpr int NPTS = 4 * BVOL;       // 3538944 = 13824 * 256

// Voxel-aligned bins: 16 x 255 x 31
static constexpr int SBX = 16, SBY = 255, SBZ = 31;
static constexpr int NB  = SBX * SBY * SBZ;    // 126480
static constexpr int CAP = 32;                 // one warp per bucket
static constexpr int NSLOTS = NB * CAP;        // 4047360

static constexpr int BUCKET_BLOCKS = NB / 8;   // 15810 (8 warps/block)
static constexpr int OVF_BLOCKS    = 1024;     // tail blocks in same grid

// ---- volume storage (fp16 half4 voxels, E/O x-pair duplicates) ----
__device__ __align__(16) uint2 g_e0[NV0];  __device__ __align__(16) uint2 g_o0[NV0];
__device__ __align__(16) uint2 g_e1[NV1];  __device__ __align__(16) uint2 g_o1[NV1];
__device__ __align__(16) uint2 g_e2[NV2];  __device__ __align__(16) uint2 g_o2[NV2];
__device__ __align__(16) uint2 g_e3[NV3];  __device__ __align__(16) uint2 g_o3[NV3];

// ---- bucket scratch ----
__device__ int    g_cnt[NB];
__device__ int    g_novf;
__device__ int    g_inv[NPTS];                 // orig idx -> result position
__device__ float4 g_sorted[NSLOTS];            // bucketed coord records
__device__ float4 g_ovf[NPTS];                 // overflow records
__device__ float4 g_res[NSLOTS + NPTS];        // results: buckets then overflow

// ---------------------------------------------------------------------------
// Pack: [3,D,H,W] fp32 -> half4 voxels in E[i] and O[i-1]; zeros counters.
// ---------------------------------------------------------------------------
__device__ __forceinline__ void pack_one(const float* __restrict__ s, int i, int nv,
                                         uint2* __restrict__ E, uint2* __restrict__ O)
{
    __half h0 = __float2half_rn(s[i]);
    __half h1 = __float2half_rn(s[i + nv]);
    __half h2 = __float2half_rn(s[i + 2 * nv]);
    __half2 lo = __halves2half2(h0, h1);
    __half2 hi = __halves2half2(h2, __ushort_as_half((unsigned short)0));
    uint2 u;
    u.x = *reinterpret_cast<unsigned int*>(&lo);
    u.y = *reinterpret_cast<unsigned int*>(&hi);
    E[i] = u;
    if (i > 0) O[i - 1] = u;
}

__global__ void __launch_bounds__(256) pack_kernel(
    const float* __restrict__ s0, const float* __restrict__ s1,
    const float* __restrict__ s2, const float* __restrict__ s3)
{
    int i = blockIdx.x * 256 + threadIdx.x;
    if (i < NB) g_cnt[i] = 0;
    if (i == 0) g_novf = 0;
    if (i < NV0) { pack_one(s0, i, NV0, g_e0, g_o0); return; }
    i -= NV0;
    if (i < NV1) { pack_one(s1, i, NV1, g_e1, g_o1); return; }
    i -= NV1;
    if (i < NV2) { pack_one(s2, i, NV2, g_e2, g_o2); return; }
    i -= NV2;
    if (i < NV3) { pack_one(s3, i, NV3, g_e3, g_o3); }
}

// ---------------------------------------------------------------------------
// Scatter: single pass; voxel-aligned key; writes record + inverse entry.
// ---------------------------------------------------------------------------
__device__ __forceinline__ int coord_key(float gx, float gy, float gz)
{
    float ux = fminf(fmaxf((gx + 1.0f) * 0.5f, 0.0f), 1.0f);
    float uy = fminf(fmaxf((gy + 1.0f) * 0.5f, 0.0f), 1.0f);
    float uz = fminf(fmaxf((gz + 1.0f) * 0.5f, 0.0f), 1.0f);
    int bx = min((int)(ux * (float)SBX), SBX - 1);
    int by = min((int)(uy * (float)SBY), SBY - 1);   // == img3 y0 lattice
    int bz = min((int)(uz * (float)SBZ), SBZ - 1);   // == z0 lattice (all vols)
    return (bz * SBY + by) * SBX + bx;
}

__global__ void __launch_bounds__(256) scatter_kernel(const float* __restrict__ coords)
{
    __shared__ float sc[768];
    int t = threadIdx.x;
    int base = blockIdx.x * 256;
    const float4* c4 = reinterpret_cast<const float4*>(coords + (size_t)base * 3);
    if (t < 192) {
        float4 v = __ldg(c4 + t);
        sc[4 * t + 0] = v.x; sc[4 * t + 1] = v.y;
        sc[4 * t + 2] = v.z; sc[4 * t + 3] = v.w;
    }
    __syncthreads();

    float gx = sc[3 * t], gy = sc[3 * t + 1], gz = sc[3 * t + 2];
    int n = base + t;
    float4 rec = make_float4(gx, gy, gz, 0.0f);
    int key = coord_key(gx, gy, gz);
    int c = atomicAdd(&g_cnt[key], 1);
    int pos;
    if (c < CAP) {
        pos = key * CAP + c;
        g_sorted[pos] = rec;
    } else {
        int j = atomicAdd(&g_novf, 1);
        g_ovf[j] = rec;
        pos = NSLOTS + j;
    }
    g_inv[n] = pos;          // coalesced in n
}

// ---------------------------------------------------------------------------
// Trilinear sample (fp32 x-lerp, fp32 accumulate).
// ---------------------------------------------------------------------------
__device__ __forceinline__ void acc_pair(uint4 q, float w, float fx,
                                         float& ax, float& ay, float& az)
{
    const __half2* h = reinterpret_cast<const __half2*>(&q);
    float2 a01 = __half22float2(h[0]);
    float  a2  = __low2float(h[1]);
    float2 b01 = __half22float2(h[2]);
    float  b2  = __low2float(h[3]);
    float cx = fmaf(fx, b01.x - a01.x, a01.x);
    float cy = fmaf(fx, b01.y - a01.y, a01.y);
    float cz = fmaf(fx, b2    - a2,    a2);
    ax = fmaf(w, cx, ax);
    ay = fmaf(w, cy, ay);
    az = fmaf(w, cz, az);
}

template <int D, int H, int W>
__device__ __forceinline__ void sample_vol(
    const uint2* __restrict__ E, const uint2* __restrict__ O,
    float gx, float gy, float gz,
    float& ax, float& ay, float& az)
{
    const float hx = 0.5f * (float)(W - 1);
    const float hy = 0.5f * (float)(H - 1);
    const float hz = 0.5f * (float)(D - 1);
    float ix = fminf(fmaxf(fmaf(gx, hx, hx), 0.0f), (float)(W - 1));
    float iy = fminf(fmaxf(fmaf(gy, hy, hy), 0.0f), (float)(H - 1));
    float iz = fminf(fmaxf(fmaf(gz, hz, hz), 0.0f), (float)(D - 1));

    int x0 = min((int)ix, W - 2);
    int y0 = min((int)iy, H - 2);
    int z0 = min((int)iz, D - 2);
    float fx = ix - (float)x0;
    float fy = iy - (float)y0;
    float fz = iz - (float)z0;

    int r00 = (z0 * H + y0) * W;
    int r01 = r00 + W;
    int r10 = r00 + H * W;
    int r11 = r10 + W;

    int odd = x0 & 1;
    const uint2* arr = odd ? O : E;
    int xo = x0 - odd;

    uint4 q00 = __ldg(reinterpret_cast<const uint4*>(arr + (r00 + xo)));
    uint4 q01 = __ldg(reinterpret_cast<const uint4*>(arr + (r01 + xo)));
    uint4 q10 = __ldg(reinterpret_cast<const uint4*>(arr + (r10 + xo)));
    uint4 q11 = __ldg(reinterpret_cast<const uint4*>(arr + (r11 + xo)));

    float ez = 1.0f - fz, ey = 1.0f - fy;
    acc_pair(q00, ez * ey, fx, ax, ay, az);
    acc_pair(q01, ez * fy, fx, ax, ay, az);
    acc_pair(q10, fz * ey, fx, ax, ay, az);
    acc_pair(q11, fz * fy, fx, ax, ay, az);
}

__device__ __forceinline__ float4 sample_all(float gx, float gy, float gz)
{
    float ax = 0.0f, ay = 0.0f, az = 0.0f;
    sample_vol<D0, H0, W0>(g_e0, g_o0, gx, gy, gz, ax, ay, az);
    sample_vol<D1, H1, W1>(g_e1, g_o1, gx, gy, gz, ax, ay, az);
    sample_vol<D2, H2, W2>(g_e2, g_o2, gx, gy, gz, ax, ay, az);
    sample_vol<D3, H3, W3>(g_e3, g_o3, gx, gy, gz, ax, ay, az);
    return make_float4(ax, ay, az, 0.0f);
}

// ---------------------------------------------------------------------------
// Fused sample: first BUCKET_BLOCKS blocks do one warp per bucket (coalesced
// g_res writes); tail OVF_BLOCKS blocks grid-stride the overflow list.
// ---------------------------------------------------------------------------
__global__ void __launch_bounds__(256) sample_kernel()
{
    if (blockIdx.x < BUCKET_BLOCKS) {
        int warp = blockIdx.x * 8 + (threadIdx.x >> 5);
        int lane = threadIdx.x & 31;
        int cnt = min(g_cnt[warp], CAP);
        if (lane < cnt) {
            int pos = warp * CAP + lane;
            float4 c = g_sorted[pos];
            g_res[pos] = sample_all(c.x, c.y, c.z);
        }
    } else {
        int total = g_novf;
        int tid = (blockIdx.x - BUCKET_BLOCKS) * 256 + threadIdx.x;
        for (int j = tid; j < total; j += OVF_BLOCKS * 256) {
            float4 c = g_ovf[j];
            g_res[NSLOTS + j] = sample_all(c.x, c.y, c.z);
        }
    }
}

// ---------------------------------------------------------------------------
// Unpermute: 4 pts/thread (4 independent 16B gathers in flight), coalesced
// output stores.
// ---------------------------------------------------------------------------
__global__ void __launch_bounds__(256) unpermute_kernel(float* __restrict__ out)
{
    int base = blockIdx.x * 1024 + threadIdx.x;

    int p0 = g_inv[base];
    int p1 = g_inv[base + 256];
    int p2 = g_inv[base + 512];
    int p3 = g_inv[base + 768];

    float4 r0 = __ldg(&g_res[p0]);
    float4 r1 = __ldg(&g_res[p1]);
    float4 r2 = __ldg(&g_res[p2]);
    float4 r3 = __ldg(&g_res[p3]);

    #pragma unroll
    for (int k = 0; k < 4; k++) {
        int m = base + k * 256;
        float4 r = (k == 0) ? r0 : (k == 1) ? r1 : (k == 2) ? r2 : r3;
        int b = m / BVOL;
        int v = m - b * BVOL;
        float* o = out + (size_t)(b * 3) * BVOL + v;
        o[0]        = r.x;
        o[BVOL]     = r.y;
        o[2 * BVOL] = r.z;
    }
}

// ---------------------------------------------------------------------------
// Launch
// ---------------------------------------------------------------------------
extern "C" void kernel_launch(void* const* d_in, const int* in_sizes, int n_in,
                              void* d_out, int out_size)
{
    const float* coords = (const float*)d_in[0];
    const float* img0   = (const float*)d_in[1];
    const float* img1   = (const float*)d_in[2];
    const float* img2   = (const float*)d_in[3];
    const float* img3   = (const float*)d_in[4];
    float*       out    = (float*)d_out;

    pack_kernel<<<NV_TOTAL / 256, 256>>>(img0, img1, img2, img3);
    scatter_kernel<<<NPTS / 256, 256>>>(coords);
    sample_kernel<<<BUCKET_BLOCKS + OVF_BLOCKS, 256>>>();
    unpermute_kernel<<<NPTS / 1024, 256>>>(out);
}